// round 2
// baseline (speedup 1.0000x reference)
#include <cuda_runtime.h>
#include <cuda_bf16.h>

// Problem constants (fixed by setup_inputs): B=2, S=2048, V=32000, WINDOW=10
#define BB 2
#define SS 2048
#define VV 32000
#define WW 10
#define TW (SS - WW)          // 2038
#define NROWS (BB * TW)       // 4076
#define LOSS_WEIGHT 0.2f

// Scratch (no device allocation allowed): per-row partial sums + dtype flag.
__device__ float g_partials[NROWS];
__device__ int   g_is64;

// ---------------------------------------------------------------------------
// Kernel 0: detect whether input_ids is int64 or int32.
// If the buffer is really int32, reading it as int64 interleaves two token ids
// into one value (v0 | v1<<32) which is astronomically larger than V; with 32
// probes the misclassification probability is ~(1/32000)^32 ~ 0.
// ---------------------------------------------------------------------------
__global__ void detect_kernel(const long long* __restrict__ p) {
    if (threadIdx.x == 0) {
        int ok = 1;
        #pragma unroll
        for (int i = 0; i < 32; i++) {
            long long v = p[i];
            if (v < 0 || v >= (long long)VV) ok = 0;
        }
        g_is64 = ok;
    }
}

// ---------------------------------------------------------------------------
// Kernel 1: one CTA per (b, t') row.
//   - stream 32000 fp32 logits of row (b, t'+W) with float4 loads,
//     accumulate sum(exp(x)) per thread (2 interleaved accumulators),
//     tree-reduce to block denominator
//   - warp 0: gather the 10 window-token logits, dedup via warp shuffles,
//     write partial = sum_j keep_j * exp(g_j) / denom  to g_partials[row]
// No atomics -> bitwise deterministic.
// ---------------------------------------------------------------------------
__global__ __launch_bounds__(256) void row_kernel(
    const float* __restrict__ logits,
    const void*  __restrict__ ids_raw)
{
    const int t = blockIdx.x;   // 0 .. TW-1
    const int b = blockIdx.y;   // 0 .. BB-1
    const int tid = threadIdx.x;

    const float* __restrict__ row =
        logits + ((size_t)(b * SS + t + WW)) * (size_t)VV;

    // ---- streaming exp-sum over the row (8000 float4 per row) ----
    const float4* __restrict__ row4 = (const float4*)row;
    float s0 = 0.0f, s1 = 0.0f;
    #pragma unroll 4
    for (int i = tid; i < VV / 4; i += 256) {
        float4 v = row4[i];
        s0 += __expf(v.x) + __expf(v.y);
        s1 += __expf(v.z) + __expf(v.w);
    }
    float s = s0 + s1;

    // warp reduce
    #pragma unroll
    for (int o = 16; o > 0; o >>= 1)
        s += __shfl_xor_sync(0xFFFFFFFFu, s, o);

    __shared__ float warp_s[8];
    __shared__ float denom_sh;
    if ((tid & 31) == 0) warp_s[tid >> 5] = s;
    __syncthreads();
    if (tid < 32) {
        float w = (tid < 8) ? warp_s[tid] : 0.0f;
        #pragma unroll
        for (int o = 4; o > 0; o >>= 1)
            w += __shfl_xor_sync(0xFFFFFFFFu, w, o);
        if (tid == 0) denom_sh = w;
    }
    __syncthreads();

    // ---- gather + dedup + partial (warp 0 only) ----
    if (tid < 32) {
        const int j = tid;
        const int is64 = g_is64;

        long long id;
        if (j < WW) {
            const int idx = b * SS + t + j;     // window tokens: input_ids[b, t .. t+W-1]
            id = is64 ? ((const long long*)ids_raw)[idx]
                      : (long long)((const int*)ids_raw)[idx];
        } else {
            id = (long long)(-1 - j);           // distinct sentinel, never matches
        }

        // keep_j = no earlier k<j with same id (all 32 lanes join the shuffles)
        int keep = (j < WW);
        #pragma unroll
        for (int k = 0; k < WW; k++) {
            long long idk = __shfl_sync(0xFFFFFFFFu, id, k);
            if (k < j && idk == id) keep = 0;
        }

        float val = 0.0f;
        if (keep) val = __expf(row[(int)id]);

        #pragma unroll
        for (int o = 16; o > 0; o >>= 1)
            val += __shfl_xor_sync(0xFFFFFFFFu, val, o);

        if (tid == 0)
            g_partials[b * TW + t] = val / denom_sh;
    }
}

// ---------------------------------------------------------------------------
// Kernel 2: deterministic fixed-order reduction of the 4076 partials.
// ---------------------------------------------------------------------------
__global__ __launch_bounds__(1024) void final_reduce_kernel(float* __restrict__ out) {
    __shared__ float sm[1024];
    const int tid = threadIdx.x;

    float s = 0.0f;
    for (int i = tid; i < NROWS; i += 1024)
        s += g_partials[i];
    sm[tid] = s;
    __syncthreads();

    #pragma unroll
    for (int stride = 512; stride > 0; stride >>= 1) {
        if (tid < stride) sm[tid] += sm[tid + stride];
        __syncthreads();
    }

    if (tid == 0)
        out[0] = LOSS_WEIGHT * sm[0] / (float)(BB * TW);
}

// ---------------------------------------------------------------------------
extern "C" void kernel_launch(void* const* d_in, const int* in_sizes, int n_in,
                              void* d_out, int out_size) {
    const float* logits = (const float*)d_in[0];
    const void*  ids    = d_in[1];

    detect_kernel<<<1, 32>>>((const long long*)ids);

    dim3 grid(TW, BB);
    row_kernel<<<grid, 256>>>(logits, ids);

    final_reduce_kernel<<<1, 1024>>>((float*)d_out);
}